// round 11
// baseline (speedup 1.0000x reference)
#include <cuda_runtime.h>
#include <cuda_bf16.h>

#define R_ROWS 4              // output rows per warp-strip
#define NROWS  (R_ROWS + 2)   // pixel rows streamed (with vertical halo)

// ---- packed fp32x2 helpers (sm_103a FFMA2 path); carried as u64 for asm "l" ----
typedef unsigned long long p2_t;

__device__ __forceinline__ p2_t ffma2(p2_t a, p2_t b, p2_t c) {
    p2_t d;
    asm("fma.rn.f32x2 %0, %1, %2, %3;" : "=l"(d) : "l"(a), "l"(b), "l"(c));
    return d;
}
__device__ __forceinline__ p2_t fadd2(p2_t a, p2_t b) {
    p2_t d;
    asm("add.rn.f32x2 %0, %1, %2;" : "=l"(d) : "l"(a), "l"(b));
    return d;
}
__device__ __forceinline__ p2_t pack2(float lo, float hi) {
    p2_t d;
    asm("mov.b64 %0, {%1, %2};" : "=l"(d) : "f"(lo), "f"(hi));
    return d;
}
__device__ __forceinline__ float2 unpack2(p2_t d) {
    float2 r;
    asm("mov.b64 {%0, %1}, %2;" : "=f"(r.x), "=f"(r.y) : "l"(d));
    return r;
}

// KAN 3x3 conv, shared KANLinear(9->1), cubic B-spline on uniform grid.
// Warp-per-strip register-rolling design (R=4), fp32 tables, packed f32x2 math:
//  - per pixel, features pack in pairs with a COMMON accumulator target:
//      even px (kw0,kw1) -> (accO, accE),  odd px (kw1,kw2) -> (accO, accE)
//    evaluated with FFMA2 Horner chains; leftover scalar feature per kh is
//    exactly the shuffle-send value.
//  - accumulators packed (accO, accE) per rolling row; shuffle contributions
//    packed and added with one f32x2 add.
__global__ __launch_bounds__(128, 7)
void kan_conv_kernel(const float* __restrict__ x,
                     const float* __restrict__ bw,
                     const float* __restrict__ sw,
                     const float* __restrict__ ss,
                     float* __restrict__ out)
{
    __shared__ float4     stag[12 * 9];       // [j][f] scalar coeffs (a0,a1,a2,a3); j=11 zero
    __shared__ ulonglong2 tabA[12 * 3 * 2];   // [j][kh] pair (kw0,kw1): {(a0p,a1p),(a2p,a3p)}
    __shared__ ulonglong2 tabB[12 * 3 * 2];   // [j][kh] pair (kw1,kw2)
    __shared__ float      Zs[9];              // spline value at padding pixels (x=0)

    const int lane  = threadIdx.x & 31;
    const int warp  = threadIdx.x >> 5;
    const int img   = blockIdx.x >> 2;                  // 1024 blocks = 256 images x 4
    const int strip = ((blockIdx.x & 3) << 2) | warp;   // 0..15
    const int y0    = strip * R_ROWS;

    // ---- stage scalar coefficient table ----
    // a0=(W0+4W1+W2)/6, a1=(W2-W0)/2, a2=(W0-2W1+W2)/2, a3=(W3-W0+3(W1-W2))/6
    if (threadIdx.x < 108) {
        const int t = threadIdx.x;
        const int j = t / 9, f = t - j * 9;
        float a0 = 0.f, a1 = 0.f, a2 = 0.f, a3 = 0.f;
        if (j < 11) {
            float scale = __ldg(&ss[f]);
            float W[4];
            #pragma unroll
            for (int c = 0; c < 4; c++) {
                int bi = j + c - 3;
                W[c] = (bi >= 0 && bi < 8) ? __ldg(&sw[f * 8 + bi]) * scale : 0.f;
            }
            const float S = 1.f / 6.f;
            a0 = (W[0] + 4.f * W[1] + W[2]) * S;
            a1 = (W[2] - W[0]) * 0.5f;
            a2 = (W[0] - 2.f * W[1] + W[2]) * 0.5f;
            a3 = (W[3] - W[0] + 3.f * (W[1] - W[2])) * S;
        }
        stag[t] = make_float4(a0, a1, a2, a3);
        // padding pixel value: x=0 -> cell j=5, u=0.5, silu=0
        if (j == 5) Zs[f] = fmaf(fmaf(fmaf(a3, 0.5f, a2), 0.5f, a1), 0.5f, a0);
    }
    float bwr[9];
    #pragma unroll
    for (int f = 0; f < 9; f++) bwr[f] = __ldg(&bw[f]);
    __syncthreads();

    // ---- build packed pair tables ----
    if (threadIdx.x < 72) {
        const int which = threadIdx.x / 36;       // 0 = A, 1 = B
        const int e = threadIdx.x % 36;
        const int j = e / 3, kh = e - j * 3;
        const int f0 = kh * 3 + which;
        float4 c0 = stag[j * 9 + f0];
        float4 c1 = stag[j * 9 + f0 + 1];
        ulonglong2* dst = (which ? tabB : tabA) + e * 2;
        dst[0] = make_ulonglong2(pack2(c0.x, c1.x), pack2(c0.y, c1.y));  // (a0p, a1p)
        dst[1] = make_ulonglong2(pack2(c0.z, c1.z), pack2(c0.w, c1.w));  // (a2p, a3p)
    }
    __syncthreads();

    float Z[9];
    #pragma unroll
    for (int f = 0; f < 9; f++) Z[f] = Zs[f];
    p2_t bwPA[3], bwPB[3];
    #pragma unroll
    for (int kh = 0; kh < 3; kh++) {
        bwPA[kh] = pack2(bwr[kh * 3 + 0], bwr[kh * 3 + 1]);
        bwPB[kh] = pack2(bwr[kh * 3 + 1], bwr[kh * 3 + 2]);
    }

    const float* xcol = x   + img * 4096 + lane * 2;
    float*       ocol = out + img * 4096 + lane * 2;

    p2_t AccP[3];                       // packed (accO, accE) rolling rows
    AccP[0] = AccP[1] = AccP[2] = pack2(0.f, 0.f);

    #pragma unroll
    for (int r = 0; r < NROWS; r++) {
        const int py = y0 - 1 + r;                 // pixel row
        float2 p = make_float2(0.f, 0.f);          // zero padding outside image
        if (py >= 0 && py < 64) p = *(const float2*)(xcol + py * 64);

        const float ve = p.x, vo = p.y;
        const float se = ve * __frcp_rn(1.f + __expf(-ve));
        const float so = vo * __frcp_rn(1.f + __expf(-vo));

        float xce = fmaf(ve, 2.5f, 5.5f);          // (v+2.2)/0.4
        float jfe = floorf(xce);
        float ue  = xce - jfe;
        int   je  = (int)jfe;
        if ((unsigned)je > 10u) { je = 11; ue = 0.f; }   // zero row of tables

        float xco = fmaf(vo, 2.5f, 5.5f);
        float jfo = floorf(xco);
        float uo  = xco - jfo;
        int   jo  = (int)jfo;
        if ((unsigned)jo > 10u) { jo = 11; uo = 0.f; }

        const p2_t u2e = pack2(ue, ue), s2e = pack2(se, se);
        const p2_t u2o = pack2(uo, uo), s2o = pack2(so, so);
        const int be = je * 3, bo = jo * 3;
        const int se9 = je * 9, so9 = jo * 9;

        // pixel row py with kh serves out row py+1-kh -> slot [2-kh].
        float sendL[3], sendR[3];
        #pragma unroll
        for (int kh = 0; kh < 3; kh++) {
            // even pixel pair (kw0 -> accO, kw1 -> accE)
            {
                ulonglong2 q0 = tabA[(be + kh) * 2];
                ulonglong2 q1 = tabA[(be + kh) * 2 + 1];
                p2_t t = ffma2(q1.y, u2e, q1.x);
                t = ffma2(t, u2e, q0.y);
                t = ffma2(t, u2e, q0.x);
                AccP[2 - kh] = fadd2(AccP[2 - kh], ffma2(s2e, bwPA[kh], t));
            }
            // even pixel scalar kw2 -> sendL (lane-1's odd col)
            {
                float4 c = stag[se9 + kh * 3 + 2];
                float t = fmaf(c.w, ue, c.z);
                t = fmaf(t, ue, c.y);
                t = fmaf(t, ue, c.x);
                sendL[kh] = fmaf(se, bwr[kh * 3 + 2], t);
            }
            // odd pixel pair (kw1 -> accO, kw2 -> accE)
            {
                ulonglong2 q0 = tabB[(bo + kh) * 2];
                ulonglong2 q1 = tabB[(bo + kh) * 2 + 1];
                p2_t t = ffma2(q1.y, u2o, q1.x);
                t = ffma2(t, u2o, q0.y);
                t = ffma2(t, u2o, q0.x);
                AccP[2 - kh] = fadd2(AccP[2 - kh], ffma2(s2o, bwPB[kh], t));
            }
            // odd pixel scalar kw0 -> sendR (lane+1's even col)
            {
                float4 c = stag[so9 + kh * 3];
                float t = fmaf(c.w, uo, c.z);
                t = fmaf(t, uo, c.y);
                t = fmaf(t, uo, c.x);
                sendR[kh] = fmaf(so, bwr[kh * 3], t);
            }
        }

        // horizontal exchange; image-edge lanes receive the padding value Z
        #pragma unroll
        for (int kh = 0; kh < 3; kh++) {
            float rl = __shfl_down_sync(0xffffffffu, sendL[kh], 1);
            if (lane == 31) rl = Z[kh * 3 + 2];   // col 64 padding -> out col 63
            float rr = __shfl_up_sync(0xffffffffu, sendR[kh], 1);
            if (lane == 0)  rr = Z[kh * 3 + 0];   // col -1 padding -> out col 0
            AccP[2 - kh] = fadd2(AccP[2 - kh], pack2(rl, rr));  // rl->accO, rr->accE
        }

        // out row py-1 complete after processing pixel row py
        if (r >= 2) {
            const int oy = y0 + r - 2;
            float2 a = unpack2(AccP[0]);          // (accO, accE)
            *(float2*)(ocol + oy * 64) = make_float2(a.y, a.x);
        }
        AccP[0] = AccP[1]; AccP[1] = AccP[2]; AccP[2] = pack2(0.f, 0.f);
    }
}

extern "C" void kernel_launch(void* const* d_in, const int* in_sizes, int n_in,
                              void* d_out, int out_size) {
    const float* x  = (const float*)d_in[0];  // (8,32,64,64)
    const float* bw = (const float*)d_in[1];  // (1,9)
    const float* sw = (const float*)d_in[2];  // (1,9,8)
    const float* ss = (const float*)d_in[3];  // (1,9)
    float* out = (float*)d_out;

    // 256 images x 16 strips, 4 warp-strips per block
    kan_conv_kernel<<<1024, 128>>>(x, bw, sw, ss, out);
}

// round 12
// speedup vs baseline: 1.3732x; 1.3732x over previous
#include <cuda_runtime.h>
#include <cuda_bf16.h>
#include <cuda_fp16.h>

#define R_ROWS 4              // output rows per warp-strip
#define NROWS  (R_ROWS + 2)   // pixel rows streamed (with vertical halo)

template<int N> struct IC { static constexpr int value = N; };

// silu via fast approx: v * rcp(1 + 2^(-v*log2e))
__device__ __forceinline__ float fast_silu(float v) {
    float e, r;
    asm("ex2.approx.f32 %0, %1;" : "=f"(e) : "f"(v * -1.442695041f));
    asm("rcp.approx.f32 %0, %1;" : "=f"(r) : "f"(1.0f + e));
    return v * r;
}

// KAN 3x3 conv, shared KANLinear(9->1), cubic B-spline on uniform grid.
// Warp-per-strip register-rolling (R=4, 4 warps/block), fp16 coeff tables,
// with compile-time kh-trimming: boundary pixel rows only evaluate the
// features whose outputs lie inside this strip (36 useful evals per
// column-pair, zero halo eval waste; bit-identical to the untrimmed sum).
__global__ __launch_bounds__(128, 7)
void kan_conv_kernel(const float* __restrict__ x,
                     const float* __restrict__ bw,
                     const float* __restrict__ sw,
                     const float* __restrict__ ss,
                     float* __restrict__ out)
{
    __shared__ uint2 polyH[12 * 9];   // [cell j][feature f] = {h2(a0,a1), h2(a2,a3)}; j=11 zero
    __shared__ float Zs[9];           // spline value at padding pixels (x=0)

    const int lane  = threadIdx.x & 31;
    const int warp  = threadIdx.x >> 5;
    const int img   = blockIdx.x >> 2;                  // 1024 blocks = 256 images x 4
    const int strip = ((blockIdx.x & 3) << 2) | warp;   // 0..15
    const int y0    = strip * R_ROWS;

    // ---- build polynomial table once per block ----
    // a0=(W0+4W1+W2)/6, a1=(W2-W0)/2, a2=(W0-2W1+W2)/2, a3=(W3-W0+3(W1-W2))/6
    if (threadIdx.x < 108) {
        const int t = threadIdx.x;
        const int j = t / 9, f = t - j * 9;
        float a0 = 0.f, a1 = 0.f, a2 = 0.f, a3 = 0.f;
        if (j < 11) {
            float scale = __ldg(&ss[f]);
            float W[4];
            #pragma unroll
            for (int c = 0; c < 4; c++) {
                int bi = j + c - 3;
                W[c] = (bi >= 0 && bi < 8) ? __ldg(&sw[f * 8 + bi]) * scale : 0.f;
            }
            const float S = 1.f / 6.f;
            a0 = (W[0] + 4.f * W[1] + W[2]) * S;
            a1 = (W[2] - W[0]) * 0.5f;
            a2 = (W[0] - 2.f * W[1] + W[2]) * 0.5f;
            a3 = (W[3] - W[0] + 3.f * (W[1] - W[2])) * S;
        }
        __half2 h01 = __floats2half2_rn(a0, a1);
        __half2 h23 = __floats2half2_rn(a2, a3);
        uint2 e;
        e.x = *reinterpret_cast<unsigned*>(&h01);
        e.y = *reinterpret_cast<unsigned*>(&h23);
        polyH[t] = e;
        // padding pixel value: x=0 -> cell j=5, u=0.5, silu=0 (fp32 exact)
        if (j == 5) Zs[f] = fmaf(fmaf(fmaf(a3, 0.5f, a2), 0.5f, a1), 0.5f, a0);
    }
    float bwr[9];
    #pragma unroll
    for (int f = 0; f < 9; f++) bwr[f] = __ldg(&bw[f]);
    __syncthreads();

    float Z[9];
    #pragma unroll
    for (int f = 0; f < 9; f++) Z[f] = Zs[f];

    const float* xcol = x   + img * 4096 + lane * 2;
    float*       ocol = out + img * 4096 + lane * 2;

    float accE[3] = {0.f, 0.f, 0.f};   // even column rolling accumulators
    float accO[3] = {0.f, 0.f, 0.f};   // odd  column rolling accumulators

    // v[f] = silu*bw[f] + cubic(u); coefficients gathered as one LDS.64
    auto evalf = [&](int jbase, float u, float s, int f) {
        uint2 pk = polyH[jbase + f];
        float2 c01 = __half22float2(*reinterpret_cast<__half2*>(&pk.x));
        float2 c23 = __half22float2(*reinterpret_cast<__half2*>(&pk.y));
        float t = fmaf(c23.y, u, c23.x);
        t = fmaf(t, u, c01.y);
        t = fmaf(t, u, c01.x);
        return fmaf(s, bwr[f], t);
    };

    auto row = [&](auto rc) {
        constexpr int r = rc.value;
        const int py = y0 - 1 + r;                  // pixel row
        float2 p;
        if constexpr (r == 0 || r == NROWS - 1) {   // only first/last row can leave the image
            p = make_float2(0.f, 0.f);
            if (py >= 0 && py < 64) p = *(const float2*)(xcol + py * 64);
        } else {
            p = *(const float2*)(xcol + py * 64);
        }

        const float ve = p.x, vo = p.y;
        const float se = fast_silu(ve);
        const float so = fast_silu(vo);

        float xce = fmaf(ve, 2.5f, 5.5f);           // (v+2.2)/0.4
        float jfe = floorf(xce);
        float ue  = xce - jfe;
        int   je  = (int)jfe;
        if ((unsigned)je > 10u) { je = 11; ue = 0.f; }   // zero row of table

        float xco = fmaf(vo, 2.5f, 5.5f);
        float jfo = floorf(xco);
        float uo  = xco - jfo;
        int   jo  = (int)jfo;
        if ((unsigned)jo > 10u) { jo = 11; uo = 0.f; }

        const int jbe = je * 9;
        const int jbo = jo * 9;

        // only features whose output rows fall inside this strip:
        // out = py + 1 - kh in [y0, y0+3]  =>  kh in [r-3, r] ∩ [0,2]
        constexpr int kh_lo = (r > 3) ? (r - 3) : 0;
        constexpr int kh_hi = (r < 2) ? r : 2;
        #pragma unroll
        for (int kh = kh_lo; kh <= kh_hi; kh++) {
            float eo = evalf(jbe, ue, se, kh * 3 + 0);  // even px -> own odd col
            float ee = evalf(jbe, ue, se, kh * 3 + 1);  // even px -> own even col
            float sL = evalf(jbe, ue, se, kh * 3 + 2);  // even px -> lane-1 odd col
            float sR = evalf(jbo, uo, so, kh * 3 + 0);  // odd  px -> lane+1 even col
            float oo = evalf(jbo, uo, so, kh * 3 + 1);
            float oe = evalf(jbo, uo, so, kh * 3 + 2);

            float rl = __shfl_down_sync(0xffffffffu, sL, 1);
            if (lane == 31) rl = Z[kh * 3 + 2];         // col 64 padding -> out col 63
            float rr = __shfl_up_sync(0xffffffffu, sR, 1);
            if (lane == 0)  rr = Z[kh * 3 + 0];         // col -1 padding -> out col 0

            accO[2 - kh] += (eo + oo) + rl;
            accE[2 - kh] += (ee + oe) + rr;
        }

        // out row py-1 = y0+r-2 complete after processing pixel row py
        if constexpr (r >= 2) {
            *(float2*)(ocol + (y0 + r - 2) * 64) = make_float2(accE[0], accO[0]);
        }
        accE[0] = accE[1]; accE[1] = accE[2]; accE[2] = 0.f;
        accO[0] = accO[1]; accO[1] = accO[2]; accO[2] = 0.f;
    };

    row(IC<0>{}); row(IC<1>{}); row(IC<2>{});
    row(IC<3>{}); row(IC<4>{}); row(IC<5>{});
}

extern "C" void kernel_launch(void* const* d_in, const int* in_sizes, int n_in,
                              void* d_out, int out_size) {
    const float* x  = (const float*)d_in[0];  // (8,32,64,64)
    const float* bw = (const float*)d_in[1];  // (1,9)
    const float* sw = (const float*)d_in[2];  // (1,9,8)
    const float* ss = (const float*)d_in[3];  // (1,9)
    float* out = (float*)d_out;

    // 256 images x 16 strips, 4 warp-strips per block
    kan_conv_kernel<<<1024, 128>>>(x, bw, sw, ss, out);
}